// round 15
// baseline (speedup 1.0000x reference)
#include <cuda_runtime.h>
#include <cuda_fp16.h>
#include <cstdint>

// ---------------------------------------------------------------------------
// 2-layer GCN: h = relu(GCN(relu(GCN(x, W1, b1)), W2, b2))
// GCNConv: out = D^{-1/2}(A+I)D^{-1/2} X W + b      (edge_index is int32)
//
// R15: (1) one-kernel scan (block-local prefix + atomic base allocator;
//          segments contiguous but unordered; gather uses off+cnt);
//      (2) gather1 split in two chunks; gemm2-chunkA overlaps gather1-chunkB
//          (events only). gemm2 writes xw2 (no WAR vs gather1 reads of xw).
// ---------------------------------------------------------------------------

#define MAX_N 50000
#define MAX_E 600000
#define H 128
#define WPAD 136
#define SCAN_BLK 1024

__device__ float  g_dinv[MAX_N];
__device__ int    g_cnt[MAX_N];
__device__ int    g_off[MAX_N];
__device__ int    g_cursor[MAX_N];
__device__ int    g_alloc;           // segment allocator
__device__ int    g_csr_src[MAX_E];
__device__ __half g_xw[MAX_N * H];   // layer-1 dinv-scaled GEMM output
__device__ __half g_xw2[MAX_N * H];  // layer-2 dinv-scaled GEMM output
__device__ __half g_hh[MAX_N * H];   // layer-1 activations (fp16)

// ---------------------------------------------------------------------------
// CSR build
// ---------------------------------------------------------------------------
__global__ void zero_cnt_kernel(int* cnt, int* alloc, int n) {
    int i = blockIdx.x * blockDim.x + threadIdx.x;
    if (i < n) cnt[i] = 0;
    if (i == 0) *alloc = 0;
}

__global__ void count_kernel(const int* __restrict__ ei, int* cnt, int e) {
    int base = (blockIdx.x * blockDim.x + threadIdx.x) * 4;
    if (base + 3 < e) {
        int4 d = *reinterpret_cast<const int4*>(ei + e + base);
        atomicAdd(&cnt[d.x], 1);
        atomicAdd(&cnt[d.y], 1);
        atomicAdd(&cnt[d.z], 1);
        atomicAdd(&cnt[d.w], 1);
    } else {
        for (int k = base; k < e; k++) atomicAdd(&cnt[ei[e + k]], 1);
    }
}

// One-kernel scan: block-local exclusive prefix + atomic base allocation.
// off[i] = segment start (contiguous per node, NOT globally ordered).
__global__ void __launch_bounds__(256) scan_fused_kernel(
    const int* __restrict__ cnt, int* __restrict__ off,
    int* __restrict__ cursor, float* __restrict__ dinv,
    int* __restrict__ alloc, int n)
{
    __shared__ int ts[256];
    __shared__ int base_sh;
    const int t = threadIdx.x;
    const int base = blockIdx.x * SCAN_BLK + t * 4;

    int c0 = (base + 0 < n) ? cnt[base + 0] : 0;
    int c1 = (base + 1 < n) ? cnt[base + 1] : 0;
    int c2 = (base + 2 < n) ? cnt[base + 2] : 0;
    int c3 = (base + 3 < n) ? cnt[base + 3] : 0;

    ts[t] = c0 + c1 + c2 + c3;
    __syncthreads();
#pragma unroll
    for (int s = 1; s < 256; s <<= 1) {
        int v = (t >= s) ? ts[t - s] : 0;
        __syncthreads();
        ts[t] += v;
        __syncthreads();
    }
    if (t == 255) base_sh = atomicAdd(alloc, ts[255]);
    __syncthreads();

    int run = base_sh + ((t == 0) ? 0 : ts[t - 1]);
    if (base + 0 < n) { off[base+0]=run; cursor[base+0]=run; dinv[base+0]=rsqrtf(1.f+(float)c0); run += c0; }
    if (base + 1 < n) { off[base+1]=run; cursor[base+1]=run; dinv[base+1]=rsqrtf(1.f+(float)c1); run += c1; }
    if (base + 2 < n) { off[base+2]=run; cursor[base+2]=run; dinv[base+2]=rsqrtf(1.f+(float)c2); run += c2; }
    if (base + 3 < n) { off[base+3]=run; cursor[base+3]=run; dinv[base+3]=rsqrtf(1.f+(float)c3); }
}

__global__ void fill_kernel(const int* __restrict__ ei,
                            int* __restrict__ cursor,
                            int* __restrict__ csr_src, int e)
{
    int base = (blockIdx.x * blockDim.x + threadIdx.x) * 4;
    if (base + 3 < e) {
        int4 s = *reinterpret_cast<const int4*>(ei + base);
        int4 d = *reinterpret_cast<const int4*>(ei + e + base);
        int p0 = atomicAdd(&cursor[d.x], 1);
        int p1 = atomicAdd(&cursor[d.y], 1);
        int p2 = atomicAdd(&cursor[d.z], 1);
        int p3 = atomicAdd(&cursor[d.w], 1);
        csr_src[p0] = s.x;
        csr_src[p1] = s.y;
        csr_src[p2] = s.z;
        csr_src[p3] = s.w;
    } else {
        for (int k = base; k < e; k++) {
            int p = atomicAdd(&cursor[ei[e + k]], 1);
            csr_src[p] = ei[k];
        }
    }
}

// ---------------------------------------------------------------------------
// tf32 helpers
// ---------------------------------------------------------------------------
__device__ __forceinline__ uint32_t f2tf32(float f) {
    uint32_t r;
    asm("cvt.rna.tf32.f32 %0, %1;" : "=r"(r) : "f"(f));
    return r;
}

__device__ __forceinline__ void mma_tf32(float* c,
    uint32_t a0, uint32_t a1, uint32_t a2, uint32_t a3,
    uint32_t b0, uint32_t b1)
{
    asm volatile(
        "mma.sync.aligned.m16n8k8.row.col.f32.tf32.tf32.f32 "
        "{%0,%1,%2,%3}, {%4,%5,%6,%7}, {%8,%9}, {%0,%1,%2,%3};"
        : "+f"(c[0]), "+f"(c[1]), "+f"(c[2]), "+f"(c[3])
        : "r"(a0), "r"(a1), "r"(a2), "r"(a3), "r"(b0), "r"(b1));
}

__device__ __forceinline__ float ld_elem(const float* p)  { return *p; }
__device__ __forceinline__ float ld_elem(const __half* p) { return __half2float(*p); }

// ---------------------------------------------------------------------------
// GEMM (tensor cores, pipelined): xw(fp16) = dinv[row] * (A @ W).
// Processes rows [row0_base, row_end). A fp32 or fp16.
// ---------------------------------------------------------------------------
template <typename TA>
__global__ void __launch_bounds__(256) gemm_tf32_kernel(
    const TA* __restrict__ A, const float* __restrict__ W,
    const float* __restrict__ dinv,
    __half* __restrict__ xw, int row0_base, int row_end)
{
    extern __shared__ float Ws[];   // [128][WPAD]

    const int tid  = threadIdx.x;
    const int lane = tid & 31;
    const int warp = tid >> 5;
    const int g    = lane >> 2;
    const int t4   = lane & 3;
    const int m0   = row0_base + blockIdx.x * 128 + warp * 16;

    const float4* W4 = reinterpret_cast<const float4*>(W);
#pragma unroll
    for (int i = tid; i < 128 * 32; i += 256) {
        int r = i >> 5, c4 = i & 31;
        float4 v = W4[r * 32 + c4];
        float* dstp = &Ws[r * WPAD + c4 * 4];
        dstp[0] = __uint_as_float(f2tf32(v.x));
        dstp[1] = __uint_as_float(f2tf32(v.y));
        dstp[2] = __uint_as_float(f2tf32(v.z));
        dstp[3] = __uint_as_float(f2tf32(v.w));
    }

    float acc[16][4];
#pragma unroll
    for (int nt = 0; nt < 16; nt++)
#pragma unroll
        for (int c = 0; c < 4; c++) acc[nt][c] = 0.f;

    const int r0 = m0 + g;
    const int r1 = r0 + 8;
    const bool v0 = r0 < row_end;
    const bool v1 = r1 < row_end;
    const TA* Ar0 = A + (size_t)r0 * H;
    const TA* Ar1 = A + (size_t)r1 * H;

    __syncthreads();

    uint32_t a0 = v0 ? f2tf32(ld_elem(Ar0 + t4))     : 0u;
    uint32_t a1 = v1 ? f2tf32(ld_elem(Ar1 + t4))     : 0u;
    uint32_t a2 = v0 ? f2tf32(ld_elem(Ar0 + t4 + 4)) : 0u;
    uint32_t a3 = v1 ? f2tf32(ld_elem(Ar1 + t4 + 4)) : 0u;

#pragma unroll
    for (int kc = 0; kc < 16; kc++) {
        uint32_t na0 = 0u, na1 = 0u, na2 = 0u, na3 = 0u;
        if (kc < 15) {
            const int c0 = (kc + 1) * 8 + t4;
            na0 = v0 ? f2tf32(ld_elem(Ar0 + c0))     : 0u;
            na1 = v1 ? f2tf32(ld_elem(Ar1 + c0))     : 0u;
            na2 = v0 ? f2tf32(ld_elem(Ar0 + c0 + 4)) : 0u;
            na3 = v1 ? f2tf32(ld_elem(Ar1 + c0 + 4)) : 0u;
        }

        const float* wb0 = &Ws[(kc * 8 + t4) * WPAD];
        const float* wb1 = &Ws[(kc * 8 + t4 + 4) * WPAD];
#pragma unroll
        for (int nt = 0; nt < 16; nt++) {
            uint32_t b0 = __float_as_uint(wb0[nt * 8 + g]);
            uint32_t b1 = __float_as_uint(wb1[nt * 8 + g]);
            mma_tf32(acc[nt], a0, a1, a2, a3, b0, b1);
        }

        a0 = na0; a1 = na1; a2 = na2; a3 = na3;
    }

    const float s0 = v0 ? dinv[r0] : 0.f;
    const float s1 = v1 ? dinv[r1] : 0.f;
#pragma unroll
    for (int nt = 0; nt < 16; nt++) {
        int col = nt * 8 + 2 * t4;
        if (v0) {
            __half2 u = __float22half2_rn(
                make_float2(acc[nt][0] * s0, acc[nt][1] * s0));
            *reinterpret_cast<__half2*>(xw + (size_t)r0 * H + col) = u;
        }
        if (v1) {
            __half2 u = __float22half2_rn(
                make_float2(acc[nt][2] * s1, acc[nt][3] * s1));
            *reinterpret_cast<__half2*>(xw + (size_t)r1 * H + col) = u;
        }
    }
}

// ---------------------------------------------------------------------------
// Pull aggregation over nodes [node0, node1): one warp per node.
// Segment = [off[node], off[node] + cnt[node]).
//   out[d] = relu( dinv[d] * ( sum_{s in N(d)} xws[s] + xws[d] ) + b )
// ---------------------------------------------------------------------------
template <bool HALF_OUT>
__global__ void __launch_bounds__(256) gather_kernel(
    const int* __restrict__ csr_src,
    const int* __restrict__ off,
    const int* __restrict__ cnt,
    const float* __restrict__ dinv,
    const __half* __restrict__ xws,
    const float* __restrict__ b,
    void* __restrict__ out, int node0, int node1)
{
    int node = node0 + ((blockIdx.x * blockDim.x + threadIdx.x) >> 5);
    int lane = threadIdx.x & 31;
    if (node >= node1) return;

    const uint2* xw2 = reinterpret_cast<const uint2*>(xws);
    int j = off[node];
    const int end = j + cnt[node];

    float4 acc0 = make_float4(0.f, 0.f, 0.f, 0.f);
    float4 acc1 = make_float4(0.f, 0.f, 0.f, 0.f);

    for (; j + 1 < end; j += 2) {
        int s0 = csr_src[j];
        int s1 = csr_src[j + 1];
        uint2 u0 = xw2[(size_t)s0 * 32 + lane];
        uint2 u1 = xw2[(size_t)s1 * 32 + lane];
        float2 p0 = __half22float2(*reinterpret_cast<__half2*>(&u0.x));
        float2 q0 = __half22float2(*reinterpret_cast<__half2*>(&u0.y));
        float2 p1 = __half22float2(*reinterpret_cast<__half2*>(&u1.x));
        float2 q1 = __half22float2(*reinterpret_cast<__half2*>(&u1.y));
        acc0.x += p0.x; acc0.y += p0.y; acc0.z += q0.x; acc0.w += q0.y;
        acc1.x += p1.x; acc1.y += p1.y; acc1.z += q1.x; acc1.w += q1.y;
    }
    if (j < end) {
        int s0 = csr_src[j];
        uint2 u0 = xw2[(size_t)s0 * 32 + lane];
        float2 p0 = __half22float2(*reinterpret_cast<__half2*>(&u0.x));
        float2 q0 = __half22float2(*reinterpret_cast<__half2*>(&u0.y));
        acc0.x += p0.x; acc0.y += p0.y; acc0.z += q0.x; acc0.w += q0.y;
    }

    uint2 us = xw2[(size_t)node * 32 + lane];
    float2 ps = __half22float2(*reinterpret_cast<__half2*>(&us.x));
    float2 qs = __half22float2(*reinterpret_cast<__half2*>(&us.y));
    float dd = dinv[node];
    float4 bb = reinterpret_cast<const float4*>(b)[lane];

    float4 r;
    r.x = fmaxf(dd * (acc0.x + acc1.x + ps.x) + bb.x, 0.f);
    r.y = fmaxf(dd * (acc0.y + acc1.y + ps.y) + bb.y, 0.f);
    r.z = fmaxf(dd * (acc0.z + acc1.z + qs.x) + bb.z, 0.f);
    r.w = fmaxf(dd * (acc0.w + acc1.w + qs.y) + bb.w, 0.f);

    if (HALF_OUT) {
        __half2 h0 = __float22half2_rn(make_float2(r.x, r.y));
        __half2 h1 = __float22half2_rn(make_float2(r.z, r.w));
        uint2 o;
        o.x = *reinterpret_cast<uint32_t*>(&h0);
        o.y = *reinterpret_cast<uint32_t*>(&h1);
        reinterpret_cast<uint2*>(out)[(size_t)node * 32 + lane] = o;
    } else {
        reinterpret_cast<float4*>(out)[(size_t)node * 32 + lane] = r;
    }
}

// ---------------------------------------------------------------------------
// Launch
// ---------------------------------------------------------------------------
extern "C" void kernel_launch(void* const* d_in, const int* in_sizes, int n_in,
                              void* d_out, int out_size)
{
    const float* x  = (const float*)d_in[0];
    const int*   ei = (const int*)d_in[1];
    const float* W1 = (const float*)d_in[2];
    const float* b1 = (const float*)d_in[3];
    const float* W2 = (const float*)d_in[4];
    const float* b2 = (const float*)d_in[5];
    float* out = (float*)d_out;

    const int n = in_sizes[0] / H;       // 50000
    const int e = in_sizes[1] / 2;       // 600000

    float*  dinv;   cudaGetSymbolAddress((void**)&dinv,   g_dinv);
    int*    cnt;    cudaGetSymbolAddress((void**)&cnt,    g_cnt);
    int*    off;    cudaGetSymbolAddress((void**)&off,    g_off);
    int*    cursor; cudaGetSymbolAddress((void**)&cursor, g_cursor);
    int*    alloc;  cudaGetSymbolAddress((void**)&alloc,  g_alloc);
    int*    csr;    cudaGetSymbolAddress((void**)&csr,    g_csr_src);
    __half* xw;     cudaGetSymbolAddress((void**)&xw,     g_xw);
    __half* xw2;    cudaGetSymbolAddress((void**)&xw2,    g_xw2);
    __half* hh;     cudaGetSymbolAddress((void**)&hh,     g_hh);

    const int smem_w = 128 * WPAD * sizeof(float);   // 69,632 B
    static int init_done = 0;
    static cudaStream_t sB = 0;
    static cudaEvent_t evDinv = 0, evG1 = 0, evGA = 0, evMA = 0;
    if (!init_done) {
        cudaFuncSetAttribute(gemm_tf32_kernel<float>,
                             cudaFuncAttributeMaxDynamicSharedMemorySize, smem_w);
        cudaFuncSetAttribute(gemm_tf32_kernel<__half>,
                             cudaFuncAttributeMaxDynamicSharedMemorySize, smem_w);
        cudaStreamCreateWithFlags(&sB, cudaStreamNonBlocking);
        cudaEventCreateWithFlags(&evDinv, cudaEventDisableTiming);
        cudaEventCreateWithFlags(&evG1, cudaEventDisableTiming);
        cudaEventCreateWithFlags(&evGA, cudaEventDisableTiming);
        cudaEventCreateWithFlags(&evMA, cudaEventDisableTiming);
        init_done = 1;
    }

    const int T = 256;
    const int blocks_n  = (n + T - 1) / T;
    const int blocks_e4 = ((e + 3) / 4 + T - 1) / T;
    const int nb        = (n + SCAN_BLK - 1) / SCAN_BLK;

    // Chunk split (multiple of 128 for clean gemm tiling).
    const int n2 = ((n / 2 + 127) / 128) * 128;      // 25088
    const int gemmA = (n2 + 127) / 128;
    const int gemmB = (n - n2 + 127) / 128;
    const int gathA = ((n2) * 32 + T - 1) / T;
    const int gathB = ((n - n2) * 32 + T - 1) / T;
    const int gathF = (n * 32 + T - 1) / T;

    // CSR chain (stream 0).
    zero_cnt_kernel<<<blocks_n, T>>>(cnt, alloc, n);
    count_kernel<<<blocks_e4, T>>>(ei, cnt, e);
    scan_fused_kernel<<<nb, 256>>>(cnt, off, cursor, dinv, alloc, n);
    cudaEventRecord(evDinv, (cudaStream_t)0);

    // gemm1 on sB (needs dinv) — overlaps fill on stream 0.
    cudaStreamWaitEvent(sB, evDinv, 0);
    gemm_tf32_kernel<float><<<(n + 127) / 128, T, smem_w, sB>>>(
        x, W1, dinv, xw, 0, n);
    cudaEventRecord(evG1, sB);

    fill_kernel<<<blocks_e4, T>>>(ei, cursor, csr, e);

    // gather1 chunk A (nodes [0, n2)) -> hh
    cudaStreamWaitEvent((cudaStream_t)0, evG1, 0);
    gather_kernel<true><<<gathA, T>>>(csr, off, cnt, dinv, xw, b1, hh, 0, n2);
    cudaEventRecord(evGA, (cudaStream_t)0);

    // gemm2 chunk A on sB (rows [0, n2)) -> xw2, overlaps gather1 chunk B.
    cudaStreamWaitEvent(sB, evGA, 0);
    gemm_tf32_kernel<__half><<<gemmA, T, smem_w, sB>>>(
        hh, W2, dinv, xw2, 0, n2);
    cudaEventRecord(evMA, sB);

    // gather1 chunk B (nodes [n2, n)) -> hh
    gather_kernel<true><<<gathB, T>>>(csr, off, cnt, dinv, xw, b1, hh, n2, n);

    // gemm2 chunk B (rows [n2, n)) -> xw2
    gemm_tf32_kernel<__half><<<gemmB, T, smem_w>>>(
        hh, W2, dinv, xw2, n2, n);

    // gather2 (all nodes) -> out (fp32)
    cudaStreamWaitEvent((cudaStream_t)0, evMA, 0);
    gather_kernel<false><<<gathF, T>>>(csr, off, cnt, dinv, xw2, b2, out, 0, n);
}

// round 16
// speedup vs baseline: 1.0796x; 1.0796x over previous
#include <cuda_runtime.h>
#include <cuda_fp16.h>
#include <cstdint>

// ---------------------------------------------------------------------------
// 2-layer GCN: h = relu(GCN(relu(GCN(x, W1, b1)), W2, b2))
// GCNConv: out = D^{-1/2}(A+I)D^{-1/2} X W + b      (edge_index is int32)
//
// R16: R14 skeleton (best, 102.9us) + single-kernel scan (block-local prefix
//      + atomic base allocator; segments contiguous per node, unordered).
//      R15's chunked gather/gemm overlap dropped (LTS contention regressed).
// ---------------------------------------------------------------------------

#define MAX_N 50000
#define MAX_E 600000
#define H 128
#define WPAD 136
#define SCAN_BLK 1024

__device__ float  g_dinv[MAX_N];
__device__ int    g_cnt[MAX_N];
__device__ int    g_off[MAX_N];
__device__ int    g_cursor[MAX_N];
__device__ int    g_alloc;
__device__ int    g_csr_src[MAX_E];
__device__ __half g_xw[MAX_N * H];   // dinv-scaled GEMM output (fp16)
__device__ __half g_hh[MAX_N * H];   // layer-1 activations (fp16)

// ---------------------------------------------------------------------------
// CSR build
// ---------------------------------------------------------------------------
__global__ void zero_cnt_kernel(int* cnt, int* alloc, int n) {
    int i = blockIdx.x * blockDim.x + threadIdx.x;
    if (i < n) cnt[i] = 0;
    if (i == 0) *alloc = 0;
}

__global__ void count_kernel(const int* __restrict__ ei, int* cnt, int e) {
    int base = (blockIdx.x * blockDim.x + threadIdx.x) * 4;
    if (base + 3 < e) {
        int4 d = *reinterpret_cast<const int4*>(ei + e + base);
        atomicAdd(&cnt[d.x], 1);
        atomicAdd(&cnt[d.y], 1);
        atomicAdd(&cnt[d.z], 1);
        atomicAdd(&cnt[d.w], 1);
    } else {
        for (int k = base; k < e; k++) atomicAdd(&cnt[ei[e + k]], 1);
    }
}

// One-kernel scan: block-local exclusive prefix + atomic base allocation.
// off[i] = segment start (contiguous per node, NOT globally ordered).
__global__ void __launch_bounds__(256) scan_fused_kernel(
    const int* __restrict__ cnt, int* __restrict__ off,
    int* __restrict__ cursor, float* __restrict__ dinv,
    int* __restrict__ alloc, int n)
{
    __shared__ int ts[256];
    __shared__ int base_sh;
    const int t = threadIdx.x;
    const int base = blockIdx.x * SCAN_BLK + t * 4;

    int c0 = (base + 0 < n) ? cnt[base + 0] : 0;
    int c1 = (base + 1 < n) ? cnt[base + 1] : 0;
    int c2 = (base + 2 < n) ? cnt[base + 2] : 0;
    int c3 = (base + 3 < n) ? cnt[base + 3] : 0;

    ts[t] = c0 + c1 + c2 + c3;
    __syncthreads();
#pragma unroll
    for (int s = 1; s < 256; s <<= 1) {
        int v = (t >= s) ? ts[t - s] : 0;
        __syncthreads();
        ts[t] += v;
        __syncthreads();
    }
    if (t == 255) base_sh = atomicAdd(alloc, ts[255]);
    __syncthreads();

    int run = base_sh + ((t == 0) ? 0 : ts[t - 1]);
    if (base + 0 < n) { off[base+0]=run; cursor[base+0]=run; dinv[base+0]=rsqrtf(1.f+(float)c0); run += c0; }
    if (base + 1 < n) { off[base+1]=run; cursor[base+1]=run; dinv[base+1]=rsqrtf(1.f+(float)c1); run += c1; }
    if (base + 2 < n) { off[base+2]=run; cursor[base+2]=run; dinv[base+2]=rsqrtf(1.f+(float)c2); run += c2; }
    if (base + 3 < n) { off[base+3]=run; cursor[base+3]=run; dinv[base+3]=rsqrtf(1.f+(float)c3); }
}

__global__ void fill_kernel(const int* __restrict__ ei,
                            int* __restrict__ cursor,
                            int* __restrict__ csr_src, int e)
{
    int base = (blockIdx.x * blockDim.x + threadIdx.x) * 4;
    if (base + 3 < e) {
        int4 s = *reinterpret_cast<const int4*>(ei + base);
        int4 d = *reinterpret_cast<const int4*>(ei + e + base);
        int p0 = atomicAdd(&cursor[d.x], 1);
        int p1 = atomicAdd(&cursor[d.y], 1);
        int p2 = atomicAdd(&cursor[d.z], 1);
        int p3 = atomicAdd(&cursor[d.w], 1);
        csr_src[p0] = s.x;
        csr_src[p1] = s.y;
        csr_src[p2] = s.z;
        csr_src[p3] = s.w;
    } else {
        for (int k = base; k < e; k++) {
            int p = atomicAdd(&cursor[ei[e + k]], 1);
            csr_src[p] = ei[k];
        }
    }
}

// ---------------------------------------------------------------------------
// tf32 helpers
// ---------------------------------------------------------------------------
__device__ __forceinline__ uint32_t f2tf32(float f) {
    uint32_t r;
    asm("cvt.rna.tf32.f32 %0, %1;" : "=r"(r) : "f"(f));
    return r;
}

__device__ __forceinline__ void mma_tf32(float* c,
    uint32_t a0, uint32_t a1, uint32_t a2, uint32_t a3,
    uint32_t b0, uint32_t b1)
{
    asm volatile(
        "mma.sync.aligned.m16n8k8.row.col.f32.tf32.tf32.f32 "
        "{%0,%1,%2,%3}, {%4,%5,%6,%7}, {%8,%9}, {%0,%1,%2,%3};"
        : "+f"(c[0]), "+f"(c[1]), "+f"(c[2]), "+f"(c[3])
        : "r"(a0), "r"(a1), "r"(a2), "r"(a3), "r"(b0), "r"(b1));
}

__device__ __forceinline__ float ld_elem(const float* p)  { return *p; }
__device__ __forceinline__ float ld_elem(const __half* p) { return __half2float(*p); }

// ---------------------------------------------------------------------------
// GEMM (tensor cores, pipelined): xw(fp16) = dinv[row] * (A @ W).
// A fp32 (layer 1) or fp16 (layer 2). W fp32 -> tf32 in smem.
// ---------------------------------------------------------------------------
template <typename TA>
__global__ void __launch_bounds__(256) gemm_tf32_kernel(
    const TA* __restrict__ A, const float* __restrict__ W,
    const float* __restrict__ dinv,
    __half* __restrict__ xw, int n)
{
    extern __shared__ float Ws[];   // [128][WPAD]

    const int tid  = threadIdx.x;
    const int lane = tid & 31;
    const int warp = tid >> 5;
    const int g    = lane >> 2;
    const int t4   = lane & 3;
    const int m0   = blockIdx.x * 128 + warp * 16;

    const float4* W4 = reinterpret_cast<const float4*>(W);
#pragma unroll
    for (int i = tid; i < 128 * 32; i += 256) {
        int r = i >> 5, c4 = i & 31;
        float4 v = W4[r * 32 + c4];
        float* dstp = &Ws[r * WPAD + c4 * 4];
        dstp[0] = __uint_as_float(f2tf32(v.x));
        dstp[1] = __uint_as_float(f2tf32(v.y));
        dstp[2] = __uint_as_float(f2tf32(v.z));
        dstp[3] = __uint_as_float(f2tf32(v.w));
    }

    float acc[16][4];
#pragma unroll
    for (int nt = 0; nt < 16; nt++)
#pragma unroll
        for (int c = 0; c < 4; c++) acc[nt][c] = 0.f;

    const int r0 = m0 + g;
    const int r1 = r0 + 8;
    const bool v0 = r0 < n;
    const bool v1 = r1 < n;
    const TA* Ar0 = A + (size_t)r0 * H;
    const TA* Ar1 = A + (size_t)r1 * H;

    __syncthreads();

    uint32_t a0 = v0 ? f2tf32(ld_elem(Ar0 + t4))     : 0u;
    uint32_t a1 = v1 ? f2tf32(ld_elem(Ar1 + t4))     : 0u;
    uint32_t a2 = v0 ? f2tf32(ld_elem(Ar0 + t4 + 4)) : 0u;
    uint32_t a3 = v1 ? f2tf32(ld_elem(Ar1 + t4 + 4)) : 0u;

#pragma unroll
    for (int kc = 0; kc < 16; kc++) {
        uint32_t na0 = 0u, na1 = 0u, na2 = 0u, na3 = 0u;
        if (kc < 15) {
            const int c0 = (kc + 1) * 8 + t4;
            na0 = v0 ? f2tf32(ld_elem(Ar0 + c0))     : 0u;
            na1 = v1 ? f2tf32(ld_elem(Ar1 + c0))     : 0u;
            na2 = v0 ? f2tf32(ld_elem(Ar0 + c0 + 4)) : 0u;
            na3 = v1 ? f2tf32(ld_elem(Ar1 + c0 + 4)) : 0u;
        }

        const float* wb0 = &Ws[(kc * 8 + t4) * WPAD];
        const float* wb1 = &Ws[(kc * 8 + t4 + 4) * WPAD];
#pragma unroll
        for (int nt = 0; nt < 16; nt++) {
            uint32_t b0 = __float_as_uint(wb0[nt * 8 + g]);
            uint32_t b1 = __float_as_uint(wb1[nt * 8 + g]);
            mma_tf32(acc[nt], a0, a1, a2, a3, b0, b1);
        }

        a0 = na0; a1 = na1; a2 = na2; a3 = na3;
    }

    const float s0 = v0 ? dinv[r0] : 0.f;
    const float s1 = v1 ? dinv[r1] : 0.f;
#pragma unroll
    for (int nt = 0; nt < 16; nt++) {
        int col = nt * 8 + 2 * t4;
        if (v0) {
            __half2 u = __float22half2_rn(
                make_float2(acc[nt][0] * s0, acc[nt][1] * s0));
            *reinterpret_cast<__half2*>(xw + (size_t)r0 * H + col) = u;
        }
        if (v1) {
            __half2 u = __float22half2_rn(
                make_float2(acc[nt][2] * s1, acc[nt][3] * s1));
            *reinterpret_cast<__half2*>(xw + (size_t)r1 * H + col) = u;
        }
    }
}

// ---------------------------------------------------------------------------
// Pull aggregation: one warp per node. Segment = [off[node], off+cnt).
//   out[d] = relu( dinv[d] * ( sum_{s in N(d)} xws[s] + xws[d] ) + b )
// ---------------------------------------------------------------------------
template <bool HALF_OUT>
__global__ void __launch_bounds__(256) gather_kernel(
    const int* __restrict__ csr_src,
    const int* __restrict__ off,
    const int* __restrict__ cnt,
    const float* __restrict__ dinv,
    const __half* __restrict__ xws,
    const float* __restrict__ b,
    void* __restrict__ out, int n)
{
    int node = (blockIdx.x * blockDim.x + threadIdx.x) >> 5;
    int lane = threadIdx.x & 31;
    if (node >= n) return;

    const uint2* xw2 = reinterpret_cast<const uint2*>(xws);
    int j = off[node];
    const int end = j + cnt[node];

    float4 acc0 = make_float4(0.f, 0.f, 0.f, 0.f);
    float4 acc1 = make_float4(0.f, 0.f, 0.f, 0.f);

    for (; j + 1 < end; j += 2) {
        int s0 = csr_src[j];
        int s1 = csr_src[j + 1];
        uint2 u0 = xw2[(size_t)s0 * 32 + lane];
        uint2 u1 = xw2[(size_t)s1 * 32 + lane];
        float2 p0 = __half22float2(*reinterpret_cast<__half2*>(&u0.x));
        float2 q0 = __half22float2(*reinterpret_cast<__half2*>(&u0.y));
        float2 p1 = __half22float2(*reinterpret_cast<__half2*>(&u1.x));
        float2 q1 = __half22float2(*reinterpret_cast<__half2*>(&u1.y));
        acc0.x += p0.x; acc0.y += p0.y; acc0.z += q0.x; acc0.w += q0.y;
        acc1.x += p1.x; acc1.y += p1.y; acc1.z += q1.x; acc1.w += q1.y;
    }
    if (j < end) {
        int s0 = csr_src[j];
        uint2 u0 = xw2[(size_t)s0 * 32 + lane];
        float2 p0 = __half22float2(*reinterpret_cast<__half2*>(&u0.x));
        float2 q0 = __half22float2(*reinterpret_cast<__half2*>(&u0.y));
        acc0.x += p0.x; acc0.y += p0.y; acc0.z += q0.x; acc0.w += q0.y;
    }

    uint2 us = xw2[(size_t)node * 32 + lane];
    float2 ps = __half22float2(*reinterpret_cast<__half2*>(&us.x));
    float2 qs = __half22float2(*reinterpret_cast<__half2*>(&us.y));
    float dd = dinv[node];
    float4 bb = reinterpret_cast<const float4*>(b)[lane];

    float4 r;
    r.x = fmaxf(dd * (acc0.x + acc1.x + ps.x) + bb.x, 0.f);
    r.y = fmaxf(dd * (acc0.y + acc1.y + ps.y) + bb.y, 0.f);
    r.z = fmaxf(dd * (acc0.z + acc1.z + qs.x) + bb.z, 0.f);
    r.w = fmaxf(dd * (acc0.w + acc1.w + qs.y) + bb.w, 0.f);

    if (HALF_OUT) {
        __half2 h0 = __float22half2_rn(make_float2(r.x, r.y));
        __half2 h1 = __float22half2_rn(make_float2(r.z, r.w));
        uint2 o;
        o.x = *reinterpret_cast<uint32_t*>(&h0);
        o.y = *reinterpret_cast<uint32_t*>(&h1);
        reinterpret_cast<uint2*>(out)[(size_t)node * 32 + lane] = o;
    } else {
        reinterpret_cast<float4*>(out)[(size_t)node * 32 + lane] = r;
    }
}

// ---------------------------------------------------------------------------
// Launch: CSR chain -> dinv; gemm1 (on sB, waits dinv) overlaps fill.
// ---------------------------------------------------------------------------
extern "C" void kernel_launch(void* const* d_in, const int* in_sizes, int n_in,
                              void* d_out, int out_size)
{
    const float* x  = (const float*)d_in[0];
    const int*   ei = (const int*)d_in[1];
    const float* W1 = (const float*)d_in[2];
    const float* b1 = (const float*)d_in[3];
    const float* W2 = (const float*)d_in[4];
    const float* b2 = (const float*)d_in[5];
    float* out = (float*)d_out;

    const int n = in_sizes[0] / H;       // 50000
    const int e = in_sizes[1] / 2;       // 600000

    float*  dinv;   cudaGetSymbolAddress((void**)&dinv,   g_dinv);
    int*    cnt;    cudaGetSymbolAddress((void**)&cnt,    g_cnt);
    int*    off;    cudaGetSymbolAddress((void**)&off,    g_off);
    int*    cursor; cudaGetSymbolAddress((void**)&cursor, g_cursor);
    int*    alloc;  cudaGetSymbolAddress((void**)&alloc,  g_alloc);
    int*    csr;    cudaGetSymbolAddress((void**)&csr,    g_csr_src);
    __half* xw;     cudaGetSymbolAddress((void**)&xw,     g_xw);
    __half* hh;     cudaGetSymbolAddress((void**)&hh,     g_hh);

    const int smem_w = 128 * WPAD * sizeof(float);   // 69,632 B
    static int init_done = 0;
    static cudaStream_t sB = 0;
    static cudaEvent_t evDinv = 0, evJoin = 0;
    if (!init_done) {
        cudaFuncSetAttribute(gemm_tf32_kernel<float>,
                             cudaFuncAttributeMaxDynamicSharedMemorySize, smem_w);
        cudaFuncSetAttribute(gemm_tf32_kernel<__half>,
                             cudaFuncAttributeMaxDynamicSharedMemorySize, smem_w);
        cudaStreamCreateWithFlags(&sB, cudaStreamNonBlocking);
        cudaEventCreateWithFlags(&evDinv, cudaEventDisableTiming);
        cudaEventCreateWithFlags(&evJoin, cudaEventDisableTiming);
        init_done = 1;
    }

    const int T = 256;
    const int blocks_n    = (n + T - 1) / T;
    const int blocks_e4   = ((e + 3) / 4 + T - 1) / T;
    const int blocks_gemm = (n + 127) / 128;
    const int blocks_gath = (n * 32 + T - 1) / T;
    const int nb          = (n + SCAN_BLK - 1) / SCAN_BLK;

    // CSR chain (stream 0): produces dinv/off/cursor in one scan kernel.
    zero_cnt_kernel<<<blocks_n, T>>>(cnt, alloc, n);
    count_kernel<<<blocks_e4, T>>>(ei, cnt, e);
    scan_fused_kernel<<<nb, 256>>>(cnt, off, cursor, dinv, alloc, n);
    cudaEventRecord(evDinv, (cudaStream_t)0);

    // gemm1 on sB (needs x, W1, dinv) — overlaps fill on stream 0.
    cudaStreamWaitEvent(sB, evDinv, 0);
    gemm_tf32_kernel<float><<<blocks_gemm, T, smem_w, sB>>>(x, W1, dinv, xw, n);
    cudaEventRecord(evJoin, sB);

    fill_kernel<<<blocks_e4, T>>>(ei, cursor, csr, e);

    // gather-1 (needs CSR + xw): h (fp16).
    cudaStreamWaitEvent((cudaStream_t)0, evJoin, 0);
    gather_kernel<true><<<blocks_gath, T>>>(csr, off, cnt, dinv, xw, b1, hh, n);

    // layer 2
    gemm_tf32_kernel<__half><<<blocks_gemm, T, smem_w>>>(hh, W2, dinv, xw, n);
    gather_kernel<false><<<blocks_gath, T>>>(csr, off, cnt, dinv, xw, b2, out, n);
}